// round 3
// baseline (speedup 1.0000x reference)
#include <cuda_runtime.h>
#include <cuda_bf16.h>
#include <cstdint>
#include <cstddef>

// Problem constants (fixed by the dataset generator)
#define NN 50000
#define DD 128
#define EE 800000
#define KTOT 1152          // 128*8 spline + 128 silu features
#define EPS_F 0.001f

// GEMM tiling
#define BM 128
#define BN 128
#define BK 64
#define GSTAGES 3
#define STAGE_BYTES ((BM*BK + BN*BK)*2)      // 32 KB
#define GSMEM_TOTAL (GSTAGES*STAGE_BYTES)    // 96 KB

// ---------------- scratch (device globals: no cudaMalloc allowed) ----------------
__device__ __align__(16) __nv_bfloat16 g_act[(size_t)NN*KTOT];   // 115 MB activations
__device__ __align__(16) float g_out[(size_t)NN*DD];             // partial KAN output (branch 1)
__device__ __align__(16) float g_agg[(size_t)NN*DD];             // GCN aggregation
__device__ __align__(16) float g_h1[(size_t)NN*DD];              // state after step 1
__device__ __align__(16) __nv_bfloat16 g_Wl[DD*KTOT];
__device__ __align__(16) __nv_bfloat16 g_Wc[DD*KTOT];
__device__ int   g_rowptr[NN+1];
__device__ int   g_deg[NN];
__device__ int   g_off[NN];
__device__ float g_dis[NN];
__device__ int   g_col[EE];
__device__ float g_w[EE];
__device__ int   g_is64;

// ---------------- edge index dtype handling ----------------
__device__ __forceinline__ int edge_src(const void* ei, int e, int E){
    return g_is64 ? (int)((const long long*)ei)[e] : ((const int*)ei)[e];
}
__device__ __forceinline__ int edge_dst(const void* ei, int e, int E){
    return g_is64 ? (int)((const long long*)ei)[(size_t)E + e]
                  : ((const int*)ei)[(size_t)E + e];
}

// zero counters + default int64 flag
__global__ void zero_kernel(){
    int i = blockIdx.x*blockDim.x + threadIdx.x;
    if (i < NN){ g_deg[i] = 0; g_off[i] = 0; }
    if (i == 0) g_is64 = 1;
}

// if dtype is int32, odd words are src[1],src[3],... (random in [0,50000)) -> some nonzero.
// if int64 (values < 2^31), every odd word is 0.
__global__ void detect_kernel(const int* ei){
    int i = blockIdx.x*blockDim.x + threadIdx.x;   // 2048 threads
    if (i < 2048){
        if (ei[2*i + 1] != 0) g_is64 = 0;          // benign race: all writers write 0
    }
}

__global__ void deg_kernel(const void* ei, int E){
    int e = blockIdx.x*blockDim.x + threadIdx.x;
    if (e < E) atomicAdd(&g_deg[edge_dst(ei, e, E)], 1);
}

// single-block exclusive scan of in-degrees -> rowptr ; also dis = rsqrt(deg+1)
__global__ void scan_kernel(){
    __shared__ int buf[1024];
    __shared__ int carry;
    int tid = threadIdx.x;
    if (tid == 0) carry = 0;
    __syncthreads();
    for (int base = 0; base < NN; base += 1024){
        int i = base + tid;
        int d = (i < NN) ? g_deg[i] : 0;
        if (i < NN) g_dis[i] = rsqrtf((float)d + 1.0f);
        buf[tid] = d; __syncthreads();
        for (int off = 1; off < 1024; off <<= 1){
            int t = (tid >= off) ? buf[tid-off] : 0;
            __syncthreads();
            buf[tid] += t;
            __syncthreads();
        }
        int incl = buf[tid];
        int c = carry;
        if (i < NN) g_rowptr[i] = c + incl - d;
        __syncthreads();
        if (tid == 1023) carry = c + buf[1023];
        __syncthreads();
    }
    if (tid == 0) g_rowptr[NN] = carry;
}

__global__ void fill_kernel(const void* ei, int E){
    int e = blockIdx.x*blockDim.x + threadIdx.x;
    if (e < E){
        int s = edge_src(ei, e, E);
        int d = edge_dst(ei, e, E);
        int p = g_rowptr[d] + atomicAdd(&g_off[d], 1);
        g_col[p] = s;
        g_w[p]   = g_dis[s] * g_dis[d];
    }
}

// pack [base_w | spline_w] into bf16 combined weights, K layout: k<1024 -> (i=k/8,b=k%8), k>=1024 -> base i
__global__ void pack_kernel(const float* __restrict__ bwl, const float* __restrict__ swl,
                            const float* __restrict__ bwc, const float* __restrict__ swc){
    int idx = blockIdx.x*blockDim.x + threadIdx.x;
    if (idx >= DD*KTOT) return;
    int o = idx / KTOT, k = idx % KTOT;
    float vl, vc;
    if (k < 1024){
        int i = k >> 3, b = k & 7;
        vl = swl[((o*DD) + i)*8 + b];
        vc = swc[((o*DD) + i)*8 + b];
    } else {
        vl = bwl[o*DD + (k - 1024)];
        vc = bwc[o*DD + (k - 1024)];
    }
    g_Wl[idx] = __float2bfloat16(vl);
    g_Wc[idx] = __float2bfloat16(vc);
}

// activations: silu + cubic B-spline bases (Cox-de Boor, identical recursion to reference)
__global__ void act_kernel(const float* __restrict__ h){
    int idx = blockIdx.x*blockDim.x + threadIdx.x;
    if (idx >= NN*DD) return;
    int n = idx >> 7, i = idx & 127;
    float x = h[idx];
    float sil = x * (1.0f / (1.0f + __expf(-x)));
    float kn[12];
    #pragma unroll
    for (int t = 0; t < 12; t++) kn[t] = (float)(t-3) * 0.4f - 1.0f;
    float b[11];
    #pragma unroll
    for (int t = 0; t < 11; t++) b[t] = (x >= kn[t] && x < kn[t+1]) ? 1.0f : 0.0f;
    #pragma unroll
    for (int j = 1; j <= 3; j++){
        #pragma unroll
        for (int t = 0; t + j < 11; t++){
            float left  = (x - kn[t])     * (1.0f/(kn[t+j]   - kn[t]));
            float right = (kn[t+j+1] - x) * (1.0f/(kn[t+j+1] - kn[t+1]));
            b[t] = left*b[t] + right*b[t+1];
        }
    }
    union { __nv_bfloat16 v[8]; uint4 u; } pk;
    #pragma unroll
    for (int t = 0; t < 8; t++) pk.v[t] = __float2bfloat16(b[t]);
    *reinterpret_cast<uint4*>(g_act + (size_t)n*KTOT + i*8) = pk.u;
    g_act[(size_t)n*KTOT + 1024 + i] = __float2bfloat16(sil);
}

// CSR gather aggregation: 1 warp per dst node, float4 per lane (h row = 512B coalesced read)
__global__ void agg_kernel(const float* __restrict__ h){
    int w = (blockIdx.x*blockDim.x + threadIdx.x) >> 5;
    if (w >= NN) return;
    int lane = threadIdx.x & 31;
    int beg = g_rowptr[w], end = g_rowptr[w+1];
    float4 acc = make_float4(0.f, 0.f, 0.f, 0.f);
    for (int e = beg; e < end; e++){
        int s = g_col[e];
        float wt = g_w[e];
        float4 v = *reinterpret_cast<const float4*>(h + (size_t)s*DD + lane*4);
        acc.x += wt*v.x; acc.y += wt*v.y; acc.z += wt*v.z; acc.w += wt*v.w;
    }
    *reinterpret_cast<float4*>(g_agg + (size_t)w*DD + lane*4) = acc;
}

// ---------------- bf16 mma GEMM: V[M,128] = A[M,1152] @ W[128,1152]^T ----------------
// mode 0: C = V                      (first KAN branch of a step)
// mode 1: hout = hin + EPS*(C + V)   (second branch + fused Euler update)
__device__ __forceinline__ uint32_t swz(uint32_t o){ return o ^ ((o >> 3) & 0x70); }

__device__ __forceinline__ void cp_async16(uint32_t saddr, const void* g, int sz){
    asm volatile("cp.async.cg.shared.global [%0], [%1], 16, %2;" :: "r"(saddr), "l"(g), "r"(sz));
}

__global__ __launch_bounds__(256) void gemm_kernel(const __nv_bfloat16* __restrict__ A,
                                                   const __nv_bfloat16* __restrict__ W,
                                                   float* __restrict__ C,
                                                   const float* __restrict__ hin,
                                                   float* __restrict__ hout,
                                                   int M, int mode)
{
    extern __shared__ char smem[];
    uint32_t sbase = (uint32_t)__cvta_generic_to_shared(smem);
    int tid  = threadIdx.x;
    int lane = tid & 31;
    int warp = tid >> 5;
    int wm = warp & 1;     // 2 warps over M (64 each)
    int wn = warp >> 1;    // 4 warps over N (32 each)
    int m0 = blockIdx.x * BM;
    const int KITERS = KTOT / BK;   // 18

    auto load_stage = [&](int kt, int stage){
        int k0 = kt * BK;
        uint32_t sA = sbase + stage*STAGE_BYTES;
        uint32_t sB = sA + BM*BK*2;
        #pragma unroll
        for (int r = 0; r < 4; r++){
            int idx = tid + r*256;
            int row = idx >> 3, c16 = idx & 7;
            int m = m0 + row;
            const char* g = (const char*)(A + (size_t)m*KTOT + k0) + c16*16;
            cp_async16(sA + swz(row*128 + c16*16), g, (m < M) ? 16 : 0);
        }
        #pragma unroll
        for (int r = 0; r < 4; r++){
            int idx = tid + r*256;
            int row = idx >> 3, c16 = idx & 7;
            const char* g = (const char*)(W + (size_t)row*KTOT + k0) + c16*16;
            cp_async16(sB + swz(row*128 + c16*16), g, 16);
        }
        asm volatile("cp.async.commit_group;");
    };

    float acc[4][4][4];
    #pragma unroll
    for (int a0 = 0; a0 < 4; a0++)
        #pragma unroll
        for (int a1 = 0; a1 < 4; a1++)
            #pragma unroll
            for (int a2 = 0; a2 < 4; a2++) acc[a0][a1][a2] = 0.f;

    load_stage(0, 0);
    load_stage(1, 1);

    for (int kt = 0; kt < KITERS; kt++){
        asm volatile("cp.async.wait_group 1;");
        __syncthreads();
        int stage = kt % GSTAGES;
        if (kt + 2 < KITERS) load_stage(kt + 2, (kt + 2) % GSTAGES);
        else                 asm volatile("cp.async.commit_group;");

        uint32_t sA = sbase + stage*STAGE_BYTES;
        uint32_t sB = sA + BM*BK*2;
        #pragma unroll
        for (int ks = 0; ks < 4; ks++){
            uint32_t a[4][4];
            #pragma unroll
            for (int mt = 0; mt < 4; mt++){
                uint32_t addr = sA + swz((uint32_t)((wm*64 + mt*16 + (lane & 15))*128 + ks*32 + ((lane >> 4)*16)));
                asm volatile("ldmatrix.sync.aligned.m8n8.x4.shared.b16 {%0,%1,%2,%3}, [%4];"
                    : "=r"(a[mt][0]), "=r"(a[mt][1]), "=r"(a[mt][2]), "=r"(a[mt][3]) : "r"(addr));
            }
            uint32_t b[4][2];
            #pragma unroll
            for (int nt = 0; nt < 4; nt++){
                uint32_t addr = sB + swz((uint32_t)((wn*32 + nt*8 + (lane & 7))*128 + ks*32 + (((lane >> 3) & 1)*16)));
                asm volatile("ldmatrix.sync.aligned.m8n8.x2.shared.b16 {%0,%1}, [%2];"
                    : "=r"(b[nt][0]), "=r"(b[nt][1]) : "r"(addr));
            }
            #pragma unroll
            for (int mt = 0; mt < 4; mt++)
                #pragma unroll
                for (int nt = 0; nt < 4; nt++)
                    asm volatile("mma.sync.aligned.m16n8k16.row.col.f32.bf16.bf16.f32 "
                        "{%0,%1,%2,%3}, {%4,%5,%6,%7}, {%8,%9}, {%0,%1,%2,%3};"
                        : "+f"(acc[mt][nt][0]), "+f"(acc[mt][nt][1]),
                          "+f"(acc[mt][nt][2]), "+f"(acc[mt][nt][3])
                        : "r"(a[mt][0]), "r"(a[mt][1]), "r"(a[mt][2]), "r"(a[mt][3]),
                          "r"(b[nt][0]), "r"(b[nt][1]));
        }
    }

    // epilogue
    #pragma unroll
    for (int mt = 0; mt < 4; mt++){
        int mrow0 = m0 + wm*64 + mt*16 + (lane >> 2);
        #pragma unroll
        for (int nt = 0; nt < 4; nt++){
            int n = wn*32 + nt*8 + (lane & 3)*2;
            #pragma unroll
            for (int half = 0; half < 2; half++){
                int m = mrow0 + half*8;
                if (m < M){
                    size_t p = (size_t)m*DD + n;
                    float v0 = acc[mt][nt][half*2 + 0];
                    float v1 = acc[mt][nt][half*2 + 1];
                    if (mode == 0){
                        C[p]   = v0;
                        C[p+1] = v1;
                    } else {
                        // fused: hout = hin + eps*(branch1 + branch2)
                        hout[p]   = hin[p]   + EPS_F*(C[p]   + v0);
                        hout[p+1] = hin[p+1] + EPS_F*(C[p+1] + v1);
                    }
                }
            }
        }
    }
}

// ---------------- launch ----------------
extern "C" void kernel_launch(void* const* d_in, const int* in_sizes, int n_in,
                              void* d_out, int out_size)
{
    const float* x   = (const float*)d_in[0];
    const void*  ei  = d_in[1];
    const float* bwl = (const float*)d_in[2];
    const float* swl = (const float*)d_in[3];
    const float* bwc = (const float*)d_in[4];
    const float* swc = (const float*)d_in[5];
    float* out = (float*)d_out;

    int E = in_sizes[1] / 2;   // element count is 2E for both int32 and int64 reporting

    cudaFuncSetAttribute(gemm_kernel, cudaFuncAttributeMaxDynamicSharedMemorySize, GSMEM_TOTAL);

    void *p_act, *p_Wl, *p_Wc, *p_out, *p_agg, *p_h1;
    cudaGetSymbolAddress(&p_act, g_act);
    cudaGetSymbolAddress(&p_Wl,  g_Wl);
    cudaGetSymbolAddress(&p_Wc,  g_Wc);
    cudaGetSymbolAddress(&p_out, g_out);
    cudaGetSymbolAddress(&p_agg, g_agg);
    cudaGetSymbolAddress(&p_h1,  g_h1);

    const int MB = (NN + BM - 1) / BM;   // 391 GEMM blocks

    // ---- graph preprocessing (once per launch) ----
    zero_kernel<<<(NN + 255)/256, 256>>>();
    detect_kernel<<<8, 256>>>((const int*)ei);
    deg_kernel<<<(E + 255)/256, 256>>>(ei, E);
    scan_kernel<<<1, 1024>>>();
    fill_kernel<<<(E + 255)/256, 256>>>(ei, E);
    pack_kernel<<<(DD*KTOT + 255)/256, 256>>>(bwl, swl, bwc, swc);

    // ---- Euler step 1: h1 = x + eps*(KAN_l(x) + KAN_c(agg(x))) ----
    act_kernel<<<(NN*DD + 255)/256, 256>>>(x);
    gemm_kernel<<<MB, 256, GSMEM_TOTAL>>>((const __nv_bfloat16*)p_act, (const __nv_bfloat16*)p_Wl,
                                          (float*)p_out, nullptr, nullptr, NN, 0);
    agg_kernel<<<(NN + 7)/8, 256>>>(x);
    act_kernel<<<(NN*DD + 255)/256, 256>>>((const float*)p_agg);
    gemm_kernel<<<MB, 256, GSMEM_TOTAL>>>((const __nv_bfloat16*)p_act, (const __nv_bfloat16*)p_Wc,
                                          (float*)p_out, x, (float*)p_h1, NN, 1);

    // ---- Euler step 2: out = h1 + eps*(KAN_l(h1) + KAN_c(agg(h1))) ----
    act_kernel<<<(NN*DD + 255)/256, 256>>>((const float*)p_h1);
    gemm_kernel<<<MB, 256, GSMEM_TOTAL>>>((const __nv_bfloat16*)p_act, (const __nv_bfloat16*)p_Wl,
                                          (float*)p_out, nullptr, nullptr, NN, 0);
    agg_kernel<<<(NN + 7)/8, 256>>>((const float*)p_h1);
    act_kernel<<<(NN*DD + 255)/256, 256>>>((const float*)p_agg);
    gemm_kernel<<<MB, 256, GSMEM_TOTAL>>>((const __nv_bfloat16*)p_act, (const __nv_bfloat16*)p_Wc,
                                          (float*)p_out, (const float*)p_h1, out, NN, 1);
}

// round 5
// speedup vs baseline: 1.1427x; 1.1427x over previous
#include <cuda_runtime.h>
#include <cuda_bf16.h>
#include <cstdint>
#include <cstddef>

// Problem constants (fixed by the dataset generator)
#define NN 50000
#define DD 128
#define EE 800000
#define KTOT 1152          // 128*8 spline + 128 silu features
#define EPS_F 0.001f

// GEMM tiling
#define BM 128
#define BN 128
#define BK 64
#define BSTAGES 3
#define TILE_BYTES (BN*BK*2)                 // 16 KB (one B stage, also one A buf)
#define SMEM_A_OFF (BSTAGES*TILE_BYTES)      // A bufs after 3 B stages
#define GSMEM_TOTAL (SMEM_A_OFF + 2*TILE_BYTES)  // 48 + 32 = 80 KB

// scan config
#define SCAN_B 256
#define NBLK ((NN + SCAN_B - 1)/SCAN_B)      // 196

// ---------------- scratch (device globals: no cudaMalloc allowed) ----------------
__device__ __align__(16) float g_out[(size_t)NN*DD];             // partial KAN output (branch 1)
__device__ __align__(16) float g_agg[(size_t)NN*DD];             // GCN aggregation
__device__ __align__(16) float g_h1[(size_t)NN*DD];              // state after step 1
__device__ __align__(16) __nv_bfloat16 g_Wl[DD*KTOT];
__device__ __align__(16) __nv_bfloat16 g_Wc[DD*KTOT];
__device__ int   g_rowptr[NN+1];
__device__ int   g_deg[NN];
__device__ int   g_off[NN];
__device__ float g_dis[NN];
__device__ int   g_col[EE];
__device__ float g_w[EE];
__device__ int   g_part[NBLK];
__device__ int   g_partscan[NBLK];
__device__ int   g_is64;

// ---------------- edge index dtype handling ----------------
__device__ __forceinline__ int edge_src(const void* ei, int e, int E){
    return g_is64 ? (int)((const long long*)ei)[e] : ((const int*)ei)[e];
}
__device__ __forceinline__ int edge_dst(const void* ei, int e, int E){
    return g_is64 ? (int)((const long long*)ei)[(size_t)E + e]
                  : ((const int*)ei)[(size_t)E + e];
}

__global__ void zero_kernel(){
    int i = blockIdx.x*blockDim.x + threadIdx.x;
    if (i < NN){ g_deg[i] = 0; g_off[i] = 0; }
    if (i == 0) g_is64 = 1;
}

// int32 -> odd words carry src[1],src[3],... (nonzero somewhere); int64 -> odd words all 0
__global__ void detect_kernel(const int* ei){
    int i = blockIdx.x*blockDim.x + threadIdx.x;
    if (i < 2048){
        if (ei[2*i + 1] != 0) g_is64 = 0;   // benign race: all writers write 0
    }
}

__global__ void deg_kernel(const void* ei, int E){
    int e = blockIdx.x*blockDim.x + threadIdx.x;
    if (e < E) atomicAdd(&g_deg[edge_dst(ei, e, E)], 1);
}

// phase 1: per-block degree sums (+ dis = rsqrt(deg+1))
__global__ void partial_kernel(){
    __shared__ int s[SCAN_B];
    int i = blockIdx.x*SCAN_B + threadIdx.x;
    int d = (i < NN) ? g_deg[i] : 0;
    if (i < NN) g_dis[i] = rsqrtf((float)d + 1.0f);
    s[threadIdx.x] = d; __syncthreads();
    #pragma unroll
    for (int off = 128; off > 0; off >>= 1){
        if (threadIdx.x < off) s[threadIdx.x] += s[threadIdx.x + off];
        __syncthreads();
    }
    if (threadIdx.x == 0) g_part[blockIdx.x] = s[0];
}

// phase 2: exclusive scan of 196 block sums (single block)
__global__ void scanpart_kernel(){
    __shared__ int s[SCAN_B];
    int t = threadIdx.x;
    int v = (t < NBLK) ? g_part[t] : 0;
    s[t] = v; __syncthreads();
    #pragma unroll
    for (int off = 1; off < SCAN_B; off <<= 1){
        int u = (t >= off) ? s[t-off] : 0;
        __syncthreads();
        s[t] += u;
        __syncthreads();
    }
    if (t < NBLK) g_partscan[t] = s[t] - v;
    if (t == NBLK-1) g_rowptr[NN] = s[t];
}

// phase 3: block-local scan + carry-in -> rowptr
__global__ void rowptr_kernel(){
    __shared__ int s[SCAN_B];
    int i = blockIdx.x*SCAN_B + threadIdx.x;
    int d = (i < NN) ? g_deg[i] : 0;
    s[threadIdx.x] = d; __syncthreads();
    #pragma unroll
    for (int off = 1; off < SCAN_B; off <<= 1){
        int u = (threadIdx.x >= off) ? s[threadIdx.x-off] : 0;
        __syncthreads();
        s[threadIdx.x] += u;
        __syncthreads();
    }
    if (i < NN) g_rowptr[i] = g_partscan[blockIdx.x] + s[threadIdx.x] - d;
}

__global__ void fill_kernel(const void* ei, int E){
    int e = blockIdx.x*blockDim.x + threadIdx.x;
    if (e < E){
        int s = edge_src(ei, e, E);
        int d = edge_dst(ei, e, E);
        int p = g_rowptr[d] + atomicAdd(&g_off[d], 1);
        g_col[p] = s;
        g_w[p]   = g_dis[s] * g_dis[d];
    }
}

// pack [spline_w | base_w] into bf16, K layout: k<1024 -> (i=k/8, b=k%8), k>=1024 -> base feature
__global__ void pack_kernel(const float* __restrict__ bwl, const float* __restrict__ swl,
                            const float* __restrict__ bwc, const float* __restrict__ swc){
    int idx = blockIdx.x*blockDim.x + threadIdx.x;
    if (idx >= DD*KTOT) return;
    int o = idx / KTOT, k = idx % KTOT;
    float vl, vc;
    if (k < 1024){
        int i = k >> 3, b = k & 7;
        vl = swl[((o*DD) + i)*8 + b];
        vc = swc[((o*DD) + i)*8 + b];
    } else {
        vl = bwl[o*DD + (k - 1024)];
        vc = bwc[o*DD + (k - 1024)];
    }
    g_Wl[idx] = __float2bfloat16(vl);
    g_Wc[idx] = __float2bfloat16(vc);
}

// CSR gather aggregation: 1 warp per dst node, float4 per lane
__global__ void agg_kernel(const float* __restrict__ h){
    int w = (blockIdx.x*blockDim.x + threadIdx.x) >> 5;
    if (w >= NN) return;
    int lane = threadIdx.x & 31;
    int beg = g_rowptr[w], end = g_rowptr[w+1];
    float4 acc = make_float4(0.f, 0.f, 0.f, 0.f);
    for (int e = beg; e < end; e++){
        int s = g_col[e];
        float wt = g_w[e];
        float4 v = *reinterpret_cast<const float4*>(h + (size_t)s*DD + lane*4);
        acc.x += wt*v.x; acc.y += wt*v.y; acc.z += wt*v.z; acc.w += wt*v.w;
    }
    *reinterpret_cast<float4*>(g_agg + (size_t)w*DD + lane*4) = acc;
}

// ---------------- fused KAN GEMM ----------------
// Computes V[M,128] = act(h)[M,1152] @ W[128,1152]^T with act generated inline:
//   k-tile kt<16 : 8 spline bases of features kt*8 .. kt*8+7
//   k-tile 16,17 : silu of features 0..63 / 64..127
// mode 0: C = V
// mode 1: hout = hin + EPS*(C + V)   (second branch + fused Euler update)
__device__ __forceinline__ uint32_t swz(uint32_t o){ return o ^ ((o >> 3) & 0x70); }

__device__ __forceinline__ void cp_async16(uint32_t saddr, const void* g){
    asm volatile("cp.async.cg.shared.global [%0], [%1], 16;" :: "r"(saddr), "l"(g));
}

// cubic B-spline bases (Cox-de Boor) — identical arithmetic to the reference
__device__ __forceinline__ void bspline8(float x, float* out8){
    float kn[12];
    #pragma unroll
    for (int t = 0; t < 12; t++) kn[t] = (float)(t-3) * 0.4f - 1.0f;
    float b[11];
    #pragma unroll
    for (int t = 0; t < 11; t++) b[t] = (x >= kn[t] && x < kn[t+1]) ? 1.0f : 0.0f;
    #pragma unroll
    for (int j = 1; j <= 3; j++){
        #pragma unroll
        for (int t = 0; t + j < 11; t++){
            float left  = (x - kn[t])     * (1.0f/(kn[t+j]   - kn[t]));
            float right = (kn[t+j+1] - x) * (1.0f/(kn[t+j+1] - kn[t+1]));
            b[t] = left*b[t] + right*b[t+1];
        }
    }
    #pragma unroll
    for (int t = 0; t < 8; t++) out8[t] = b[t];
}

__device__ __forceinline__ float silu(float x){
    return x * (1.0f / (1.0f + __expf(-x)));
}

__global__ __launch_bounds__(256) void gemm_kernel(const float* __restrict__ h,
                                                   const __nv_bfloat16* __restrict__ W,
                                                   float* __restrict__ C,
                                                   const float* __restrict__ hin,
                                                   float* __restrict__ hout,
                                                   int M, int mode)
{
    extern __shared__ char smem[];
    uint32_t sbase = (uint32_t)__cvta_generic_to_shared(smem);
    int tid  = threadIdx.x;
    int lane = tid & 31;
    int warp = tid >> 5;
    int wm = warp & 1;     // 2 warps over M (64 each)
    int wn = warp >> 1;    // 4 warps over N (32 each)
    int m0 = blockIdx.x * BM;
    const int KITERS = KTOT / BK;   // 18

    // B stage load (weights, 3-stage cp.async pipeline)
    auto load_B = [&](int kt, int stage){
        int k0 = kt * BK;
        uint32_t sB = sbase + stage*TILE_BYTES;
        #pragma unroll
        for (int r = 0; r < 4; r++){
            int idx = tid + r*256;
            int row = idx >> 3, c16 = idx & 7;
            const char* g = (const char*)(W + (size_t)row*KTOT + k0) + c16*16;
            cp_async16(sB + swz(row*128 + c16*16), g);
        }
        asm volatile("cp.async.commit_group;");
    };

    // A tile generation: compute activations directly into staging buffer
    auto compute_A = [&](int kt, int buf){
        char* abuf = smem + SMEM_A_OFF + buf*TILE_BYTES;
        if (kt < 16){
            #pragma unroll
            for (int r = 0; r < 4; r++){
                int idx = tid + r*256;
                int row = idx >> 3, fl = idx & 7;
                int m = m0 + row;
                float x = (m < M) ? h[(size_t)m*DD + kt*8 + fl] : 0.0f;
                float bs[8];
                bspline8(x, bs);
                union { __nv_bfloat16 v[8]; uint4 u; } pk;
                #pragma unroll
                for (int t = 0; t < 8; t++) pk.v[t] = __float2bfloat16(bs[t]);
                *reinterpret_cast<uint4*>(abuf + swz(row*128 + fl*16)) = pk.u;
            }
        } else {
            int fb = (kt - 16)*64;
            #pragma unroll
            for (int r = 0; r < 4; r++){
                int idx = tid + r*256;
                int row = idx >> 3, c = idx & 7;
                int m = m0 + row;
                float4 v0 = make_float4(0.f,0.f,0.f,0.f), v1 = v0;
                if (m < M){
                    const float* p = h + (size_t)m*DD + fb + c*8;
                    v0 = *reinterpret_cast<const float4*>(p);
                    v1 = *reinterpret_cast<const float4*>(p + 4);
                }
                union { __nv_bfloat16 v[8]; uint4 u; } pk;
                pk.v[0] = __float2bfloat16(silu(v0.x));
                pk.v[1] = __float2bfloat16(silu(v0.y));
                pk.v[2] = __float2bfloat16(silu(v0.z));
                pk.v[3] = __float2bfloat16(silu(v0.w));
                pk.v[4] = __float2bfloat16(silu(v1.x));
                pk.v[5] = __float2bfloat16(silu(v1.y));
                pk.v[6] = __float2bfloat16(silu(v1.z));
                pk.v[7] = __float2bfloat16(silu(v1.w));
                *reinterpret_cast<uint4*>(abuf + swz(row*128 + c*16)) = pk.u;
            }
        }
    };

    float acc[4][4][4];
    #pragma unroll
    for (int a0 = 0; a0 < 4; a0++)
        #pragma unroll
        for (int a1 = 0; a1 < 4; a1++)
            #pragma unroll
            for (int a2 = 0; a2 < 4; a2++) acc[a0][a1][a2] = 0.f;

    load_B(0, 0);
    load_B(1, 1);
    compute_A(0, 0);

    for (int kt = 0; kt < KITERS; kt++){
        asm volatile("cp.async.wait_group 1;");
        __syncthreads();                       // B[kt] ready; A[kt%2] writes visible; prior reads done
        if (kt + 2 < KITERS) load_B(kt + 2, (kt + 2) % 3);
        else                 asm volatile("cp.async.commit_group;");

        uint32_t sA = sbase + SMEM_A_OFF + (kt & 1)*TILE_BYTES;
        uint32_t sB = sbase + (kt % 3)*TILE_BYTES;
        #pragma unroll
        for (int ks = 0; ks < 4; ks++){
            uint32_t a[4][4];
            #pragma unroll
            for (int mt = 0; mt < 4; mt++){
                uint32_t addr = sA + swz((uint32_t)((wm*64 + mt*16 + (lane & 15))*128 + ks*32 + ((lane >> 4)*16)));
                asm volatile("ldmatrix.sync.aligned.m8n8.x4.shared.b16 {%0,%1,%2,%3}, [%4];"
                    : "=r"(a[mt][0]), "=r"(a[mt][1]), "=r"(a[mt][2]), "=r"(a[mt][3]) : "r"(addr));
            }
            uint32_t b[4][2];
            #pragma unroll
            for (int nt = 0; nt < 4; nt++){
                uint32_t addr = sB + swz((uint32_t)((wn*32 + nt*8 + (lane & 7))*128 + ks*32 + (((lane >> 3) & 1)*16)));
                asm volatile("ldmatrix.sync.aligned.m8n8.x2.shared.b16 {%0,%1}, [%2];"
                    : "=r"(b[nt][0]), "=r"(b[nt][1]) : "r"(addr));
            }
            #pragma unroll
            for (int mt = 0; mt < 4; mt++)
                #pragma unroll
                for (int nt = 0; nt < 4; nt++)
                    asm volatile("mma.sync.aligned.m16n8k16.row.col.f32.bf16.bf16.f32 "
                        "{%0,%1,%2,%3}, {%4,%5,%6,%7}, {%8,%9}, {%0,%1,%2,%3};"
                        : "+f"(acc[mt][nt][0]), "+f"(acc[mt][nt][1]),
                          "+f"(acc[mt][nt][2]), "+f"(acc[mt][nt][3])
                        : "r"(a[mt][0]), "r"(a[mt][1]), "r"(a[mt][2]), "r"(a[mt][3]),
                          "r"(b[nt][0]), "r"(b[nt][1]));
        }

        // generate next A tile (FMA/MUFU pipes, overlaps tensor work); visible after next sync
        if (kt + 1 < KITERS) compute_A(kt + 1, (kt + 1) & 1);
    }

    // epilogue
    #pragma unroll
    for (int mt = 0; mt < 4; mt++){
        int mrow0 = m0 + wm*64 + mt*16 + (lane >> 2);
        #pragma unroll
        for (int nt = 0; nt < 4; nt++){
            int n = wn*32 + nt*8 + (lane & 3)*2;
            #pragma unroll
            for (int half = 0; half < 2; half++){
                int m = mrow0 + half*8;
                if (m < M){
                    size_t p = (size_t)m*DD + n;
                    float v0 = acc[mt][nt][half*2 + 0];
                    float v1 = acc[mt][nt][half*2 + 1];
                    if (mode == 0){
                        C[p]   = v0;
                        C[p+1] = v1;
                    } else {
                        hout[p]   = hin[p]   + EPS_F*(C[p]   + v0);
                        hout[p+1] = hin[p+1] + EPS_F*(C[p+1] + v1);
                    }
                }
            }
        }
    }
}

// ---------------- launch ----------------
extern "C" void kernel_launch(void* const* d_in, const int* in_sizes, int n_in,
                              void* d_out, int out_size)
{
    const float* x   = (const float*)d_in[0];
    const void*  ei  = d_in[1];
    const float* bwl = (const float*)d_in[2];
    const float* swl = (const float*)d_in[3];
    const float* bwc = (const float*)d_in[4];
    const float* swc = (const float*)d_in[5];
    float* out = (float*)d_out;

    int E = in_sizes[1] / 2;

    cudaFuncSetAttribute(gemm_kernel, cudaFuncAttributeMaxDynamicSharedMemorySize, GSMEM_TOTAL);

    void *p_Wl, *p_Wc, *p_out, *p_agg, *p_h1;
    cudaGetSymbolAddress(&p_Wl,  g_Wl);
    cudaGetSymbolAddress(&p_Wc,  g_Wc);
    cudaGetSymbolAddress(&p_out, g_out);
    cudaGetSymbolAddress(&p_agg, g_agg);
    cudaGetSymbolAddress(&p_h1,  g_h1);

    const int MB = (NN + BM - 1) / BM;   // 391 GEMM blocks

    // ---- graph preprocessing ----
    zero_kernel<<<(NN + 255)/256, 256>>>();
    detect_kernel<<<8, 256>>>((const int*)ei);
    deg_kernel<<<(E + 255)/256, 256>>>(ei, E);
    partial_kernel<<<NBLK, SCAN_B>>>();
    scanpart_kernel<<<1, SCAN_B>>>();
    rowptr_kernel<<<NBLK, SCAN_B>>>();
    fill_kernel<<<(E + 255)/256, 256>>>(ei, E);
    pack_kernel<<<(DD*KTOT + 255)/256, 256>>>(bwl, swl, bwc, swc);

    // ---- Euler step 1: h1 = x + eps*(KAN_l(x) + KAN_c(agg(x))) ----
    gemm_kernel<<<MB, 256, GSMEM_TOTAL>>>(x, (const __nv_bfloat16*)p_Wl,
                                          (float*)p_out, nullptr, nullptr, NN, 0);
    agg_kernel<<<(NN + 7)/8, 256>>>(x);
    gemm_kernel<<<MB, 256, GSMEM_TOTAL>>>((const float*)p_agg, (const __nv_bfloat16*)p_Wc,
                                          (float*)p_out, x, (float*)p_h1, NN, 1);

    // ---- Euler step 2: out = h1 + eps*(KAN_l(h1) + KAN_c(agg(h1))) ----
    gemm_kernel<<<MB, 256, GSMEM_TOTAL>>>((const float*)p_h1, (const __nv_bfloat16*)p_Wl,
                                          (float*)p_out, nullptr, nullptr, NN, 0);
    agg_kernel<<<(NN + 7)/8, 256>>>((const float*)p_h1);
    gemm_kernel<<<MB, 256, GSMEM_TOTAL>>>((const float*)p_agg, (const __nv_bfloat16*)p_Wc,
                                          (float*)p_out, (const float*)p_h1, out, NN, 1);
}

// round 12
// speedup vs baseline: 1.2823x; 1.1221x over previous
#include <cuda_runtime.h>
#include <cuda_bf16.h>
#include <cstdint>
#include <cstddef>

// Problem constants (fixed by the dataset generator)
#define NN 50000
#define DD 128
#define EE 800000
#define KTOT 1152          // 128*8 spline + 128 silu features
#define EPS_F 0.001f

// GEMM tiling
#define BM 128
#define BN 128
#define BK 64
#define BSTAGES 3
#define TILE_BYTES (BN*BK*2)                 // 16 KB (one B stage, also one A buf)
#define SMEM_A_OFF (BSTAGES*TILE_BYTES)      // A bufs after 3 B stages
#define GSMEM_TOTAL (SMEM_A_OFF + 2*TILE_BYTES)  // 48 + 32 = 80 KB

// scan config
#define SCAN_B 256
#define NBLK ((NN + SCAN_B - 1)/SCAN_B)      // 196

// ---------------- scratch (device globals: no cudaMalloc allowed) ----------------
__device__ __align__(16) float g_out[(size_t)NN*DD];             // partial KAN output (branch 1)
__device__ __align__(16) float g_agg[(size_t)NN*DD];             // GCN aggregation
__device__ __align__(16) float g_h1[(size_t)NN*DD];              // state after step 1
__device__ __align__(16) __nv_bfloat16 g_Wl[DD*KTOT];
__device__ __align__(16) __nv_bfloat16 g_Wc[DD*KTOT];
__device__ int   g_rowptr[NN+1];
__device__ int   g_deg[NN];
__device__ int   g_off[NN];
__device__ float g_dis[NN];
__device__ int   g_col[EE];
__device__ float g_w[EE];
__device__ int   g_part[NBLK];
__device__ int   g_partscan[NBLK];
__device__ int   g_is64;

// ---------------- edge index dtype handling ----------------
__device__ __forceinline__ int edge_src(const void* ei, int e, int E){
    return g_is64 ? (int)((const long long*)ei)[e] : ((const int*)ei)[e];
}
__device__ __forceinline__ int edge_dst(const void* ei, int e, int E){
    return g_is64 ? (int)((const long long*)ei)[(size_t)E + e]
                  : ((const int*)ei)[(size_t)E + e];
}

__global__ void zero_kernel(){
    int i = blockIdx.x*blockDim.x + threadIdx.x;
    if (i < NN){ g_deg[i] = 0; g_off[i] = 0; }
    if (i == 0) g_is64 = 1;
}

// int32 -> odd words carry src[1],src[3],... (nonzero somewhere); int64 -> odd words all 0
__global__ void detect_kernel(const int* ei){
    int i = blockIdx.x*blockDim.x + threadIdx.x;
    if (i < 2048){
        if (ei[2*i + 1] != 0) g_is64 = 0;   // benign race: all writers write 0
    }
}

__global__ void deg_kernel(const void* ei, int E){
    int e = blockIdx.x*blockDim.x + threadIdx.x;
    if (e < E) atomicAdd(&g_deg[edge_dst(ei, e, E)], 1);
}

// phase 1: per-block degree sums (+ dis = rsqrt(deg+1))
__global__ void partial_kernel(){
    __shared__ int s[SCAN_B];
    int i = blockIdx.x*SCAN_B + threadIdx.x;
    int d = (i < NN) ? g_deg[i] : 0;
    if (i < NN) g_dis[i] = rsqrtf((float)d + 1.0f);
    s[threadIdx.x] = d; __syncthreads();
    #pragma unroll
    for (int off = 128; off > 0; off >>= 1){
        if (threadIdx.x < off) s[threadIdx.x] += s[threadIdx.x + off];
        __syncthreads();
    }
    if (threadIdx.x == 0) g_part[blockIdx.x] = s[0];
}

// phase 2: exclusive scan of 196 block sums (single block)
__global__ void scanpart_kernel(){
    __shared__ int s[SCAN_B];
    int t = threadIdx.x;
    int v = (t < NBLK) ? g_part[t] : 0;
    s[t] = v; __syncthreads();
    #pragma unroll
    for (int off = 1; off < SCAN_B; off <<= 1){
        int u = (t >= off) ? s[t-off] : 0;
        __syncthreads();
        s[t] += u;
        __syncthreads();
    }
    if (t < NBLK) g_partscan[t] = s[t] - v;
    if (t == NBLK-1) g_rowptr[NN] = s[t];
}

// phase 3: block-local scan + carry-in -> rowptr
__global__ void rowptr_kernel(){
    __shared__ int s[SCAN_B];
    int i = blockIdx.x*SCAN_B + threadIdx.x;
    int d = (i < NN) ? g_deg[i] : 0;
    s[threadIdx.x] = d; __syncthreads();
    #pragma unroll
    for (int off = 1; off < SCAN_B; off <<= 1){
        int u = (threadIdx.x >= off) ? s[threadIdx.x-off] : 0;
        __syncthreads();
        s[threadIdx.x] += u;
        __syncthreads();
    }
    if (i < NN) g_rowptr[i] = g_partscan[blockIdx.x] + s[threadIdx.x] - d;
}

__global__ void fill_kernel(const void* ei, int E){
    int e = blockIdx.x*blockDim.x + threadIdx.x;
    if (e < E){
        int s = edge_src(ei, e, E);
        int d = edge_dst(ei, e, E);
        int p = g_rowptr[d] + atomicAdd(&g_off[d], 1);
        g_col[p] = s;
        g_w[p]   = g_dis[s] * g_dis[d];
    }
}

// pack [spline_w | base_w] into bf16, K layout: k<1024 -> (i=k/8, b=k%8), k>=1024 -> base feature
__global__ void pack_kernel(const float* __restrict__ bwl, const float* __restrict__ swl,
                            const float* __restrict__ bwc, const float* __restrict__ swc){
    int idx = blockIdx.x*blockDim.x + threadIdx.x;
    if (idx >= DD*KTOT) return;
    int o = idx / KTOT, k = idx % KTOT;
    float vl, vc;
    if (k < 1024){
        int i = k >> 3, b = k & 7;
        vl = swl[((o*DD) + i)*8 + b];
        vc = swc[((o*DD) + i)*8 + b];
    } else {
        vl = bwl[o*DD + (k - 1024)];
        vc = bwc[o*DD + (k - 1024)];
    }
    g_Wl[idx] = __float2bfloat16(vl);
    g_Wc[idx] = __float2bfloat16(vc);
}

// CSR gather aggregation: 1 warp per dst node, float4 per lane,
// 2-way edge unroll with independent accumulators (MLP 1 -> 2 on the gather chain)
__global__ void agg_kernel(const float* __restrict__ h){
    int w = (blockIdx.x*blockDim.x + threadIdx.x) >> 5;
    if (w >= NN) return;
    int lane = threadIdx.x & 31;
    int beg = g_rowptr[w], end = g_rowptr[w+1];
    float4 acc0 = make_float4(0.f, 0.f, 0.f, 0.f);
    float4 acc1 = make_float4(0.f, 0.f, 0.f, 0.f);
    int e = beg;
    for (; e + 1 < end; e += 2){
        int   s0 = g_col[e],   s1 = g_col[e+1];
        float w0 = g_w[e],     w1 = g_w[e+1];
        float4 v0 = *reinterpret_cast<const float4*>(h + (size_t)s0*DD + lane*4);
        float4 v1 = *reinterpret_cast<const float4*>(h + (size_t)s1*DD + lane*4);
        acc0.x += w0*v0.x; acc0.y += w0*v0.y; acc0.z += w0*v0.z; acc0.w += w0*v0.w;
        acc1.x += w1*v1.x; acc1.y += w1*v1.y; acc1.z += w1*v1.z; acc1.w += w1*v1.w;
    }
    if (e < end){
        int s0 = g_col[e];
        float w0 = g_w[e];
        float4 v0 = *reinterpret_cast<const float4*>(h + (size_t)s0*DD + lane*4);
        acc0.x += w0*v0.x; acc0.y += w0*v0.y; acc0.z += w0*v0.z; acc0.w += w0*v0.w;
    }
    acc0.x += acc1.x; acc0.y += acc1.y; acc0.z += acc1.z; acc0.w += acc1.w;
    *reinterpret_cast<float4*>(g_agg + (size_t)w*DD + lane*4) = acc0;
}

// ---------------- fused KAN GEMM ----------------
// Computes V[M,128] = act(h)[M,1152] @ W[128,1152]^T with act generated inline:
//   k-tile kt<16 : 8 spline bases of features kt*8 .. kt*8+7
//   k-tile 16,17 : silu of features 0..63 / 64..127
// mode 0: C = V
// mode 1: hout = hin + EPS*(C + V)   (second branch + fused Euler update)
__device__ __forceinline__ uint32_t swz(uint32_t o){ return o ^ ((o >> 3) & 0x70); }

__device__ __forceinline__ void cp_async16(uint32_t saddr, const void* g){
    asm volatile("cp.async.cg.shared.global [%0], [%1], 16;" :: "r"(saddr), "l"(g));
}

__device__ __forceinline__ float silu(float x){
    return x * (1.0f / (1.0f + __expf(-x)));
}

// Fast cardinal cubic B-spline: 8 bases packed as 4x u32 (8 bf16).
// Uniform extended grid => every basis is a translated cardinal cubic.
// s = (x + 2.2)/0.4 ; i = floor(s); nonzero bases t = i-3..i with the standard
// cubic pieces; values placed into the 8-slot vector by a 64->128 bit shift
// that self-clamps for out-of-range x (matching the reference's 8-basis truncation).
__device__ __forceinline__ void bspline8_packed(float x, uint32_t* w4){
    float s  = (x + 2.2f) * 2.5f;
    float fi = floorf(s);
    int   i  = (int)fi;
    float u  = s - fi;
    float u2 = u*u;
    float u3 = u2*u;
    float om = 1.0f - u;
    const float c6 = 1.0f/6.0f;
    float v0 = c6*om*om*om;                             // t = i-3
    float v1 = c6*(3.0f*u3 - 6.0f*u2 + 4.0f);           // t = i-2
    float v2 = c6*(-3.0f*u3 + 3.0f*u2 + 3.0f*u + 1.0f); // t = i-1
    float v3 = c6*u3;                                   // t = i
    uint32_t p01 = ((uint32_t)__bfloat16_as_ushort(__float2bfloat16(v1)) << 16)
                 |  (uint32_t)__bfloat16_as_ushort(__float2bfloat16(v0));
    uint32_t p23 = ((uint32_t)__bfloat16_as_ushort(__float2bfloat16(v3)) << 16)
                 |  (uint32_t)__bfloat16_as_ushort(__float2bfloat16(v2));
    unsigned long long lo = ((unsigned long long)p23 << 32) | p01;
    int sh = (i - 3) * 16;    // bit offset of v0 within the 128-bit output
    #pragma unroll
    for (int k = 0; k < 4; k++){
        int rs = 32*k - sh;
        uint32_t w;
        if      (rs >= 64)  w = 0u;
        else if (rs >= 0)   w = (uint32_t)(lo >> rs);
        else if (rs > -64)  w = (uint32_t)(lo << (-rs));
        else                w = 0u;
        w4[k] = w;
    }
}

__global__ __launch_bounds__(256) void gemm_kernel(const float* __restrict__ h,
                                                   const __nv_bfloat16* __restrict__ W,
                                                   float* __restrict__ C,
                                                   const float* __restrict__ hin,
                                                   float* __restrict__ hout,
                                                   int M, int mode)
{
    extern __shared__ char smem[];
    uint32_t sbase = (uint32_t)__cvta_generic_to_shared(smem);
    int tid  = threadIdx.x;
    int lane = tid & 31;
    int warp = tid >> 5;
    int wm = warp & 1;     // 2 warps over M (64 each)
    int wn = warp >> 1;    // 4 warps over N (32 each)
    int m0 = blockIdx.x * BM;
    const int KITERS = KTOT / BK;   // 18

    // B stage load (weights, 3-stage cp.async pipeline)
    auto load_B = [&](int kt, int stage){
        int k0 = kt * BK;
        uint32_t sB = sbase + stage*TILE_BYTES;
        #pragma unroll
        for (int r = 0; r < 4; r++){
            int idx = tid + r*256;
            int row = idx >> 3, c16 = idx & 7;
            const char* g = (const char*)(W + (size_t)row*KTOT + k0) + c16*16;
            cp_async16(sB + swz(row*128 + c16*16), g);
        }
        asm volatile("cp.async.commit_group;");
    };

    // A tile generation: compute activations directly into staging buffer
    auto compute_A = [&](int kt, int buf){
        char* abuf = smem + SMEM_A_OFF + buf*TILE_BYTES;
        if (kt < 16){
            #pragma unroll
            for (int r = 0; r < 4; r++){
                int idx = tid + r*256;
                int row = idx >> 3, fl = idx & 7;
                int m = m0 + row;
                float x = (m < M) ? h[(size_t)m*DD + kt*8 + fl] : 0.0f;
                uint4 pk;
                bspline8_packed(x, &pk.x);
                *reinterpret_cast<uint4*>(abuf + swz(row*128 + fl*16)) = pk;
            }
        } else {
            int fb = (kt - 16)*64;
            #pragma unroll
            for (int r = 0; r < 4; r++){
                int idx = tid + r*256;
                int row = idx >> 3, c = idx & 7;
                int m = m0 + row;
                float4 v0 = make_float4(0.f,0.f,0.f,0.f), v1 = v0;
                if (m < M){
                    const float* p = h + (size_t)m*DD + fb + c*8;
                    v0 = *reinterpret_cast<const float4*>(p);
                    v1 = *reinterpret_cast<const float4*>(p + 4);
                }
                union { __nv_bfloat16 v[8]; uint4 u; } pk;
                pk.v[0] = __float2bfloat16(silu(v0.x));
                pk.v[1] = __float2bfloat16(silu(v0.y));
                pk.v[2] = __float2bfloat16(silu(v0.z));
                pk.v[3] = __float2bfloat16(silu(v0.w));
                pk.v[4] = __float2bfloat16(silu(v1.x));
                pk.v[5] = __float2bfloat16(silu(v1.y));
                pk.v[6] = __float2bfloat16(silu(v1.z));
                pk.v[7] = __float2bfloat16(silu(v1.w));
                *reinterpret_cast<uint4*>(abuf + swz(row*128 + c*16)) = pk.u;
            }
        }
    };

    float acc[4][4][4];
    #pragma unroll
    for (int a0 = 0; a0 < 4; a0++)
        #pragma unroll
        for (int a1 = 0; a1 < 4; a1++)
            #pragma unroll
            for (int a2 = 0; a2 < 4; a2++) acc[a0][a1][a2] = 0.f;

    load_B(0, 0);
    load_B(1, 1);
    compute_A(0, 0);

    for (int kt = 0; kt < KITERS; kt++){
        asm volatile("cp.async.wait_group 1;");
        __syncthreads();                       // B[kt] ready; A[kt%2] writes visible; prior reads done
        if (kt + 2 < KITERS) load_B(kt + 2, (kt + 2) % 3);
        else                 asm volatile("cp.async.commit_group;");

        uint32_t sA = sbase + SMEM_A_OFF + (kt & 1)*TILE_BYTES;
        uint32_t sB = sbase + (kt % 3)*TILE_BYTES;
        #pragma unroll
        for (int ks = 0; ks < 4; ks++){
            uint32_t a[4][4];
            #pragma unroll
            for (int mt = 0; mt < 4; mt++){
                uint32_t addr = sA + swz((uint32_t)((wm*64 + mt*16 + (lane & 15))*128 + ks*32 + ((lane >> 4)*16)));
                asm volatile("ldmatrix.sync.aligned.m8n8.x4.shared.b16 {%0,%1,%2,%3}, [%4];"
                    : "=r"(a[mt][0]), "=r"(a[mt][1]), "=r"(a[mt][2]), "=r"(a[mt][3]) : "r"(addr));
            }
            uint32_t b[4][2];
            #pragma unroll
            for (int nt = 0; nt < 4; nt++){
                uint32_t addr = sB + swz((uint32_t)((wn*32 + nt*8 + (lane & 7))*128 + ks*32 + (((lane >> 3) & 1)*16)));
                asm volatile("ldmatrix.sync.aligned.m8n8.x2.shared.b16 {%0,%1}, [%2];"
                    : "=r"(b[nt][0]), "=r"(b[nt][1]) : "r"(addr));
            }
            #pragma unroll
            for (int mt = 0; mt < 4; mt++)
                #pragma unroll
                for (int nt = 0; nt < 4; nt++)
                    asm volatile("mma.sync.aligned.m16n8k16.row.col.f32.bf16.bf16.f32 "
                        "{%0,%1,%2,%3}, {%4,%5,%6,%7}, {%8,%9}, {%0,%1,%2,%3};"
                        : "+f"(acc[mt][nt][0]), "+f"(acc[mt][nt][1]),
                          "+f"(acc[mt][nt][2]), "+f"(acc[mt][nt][3])
                        : "r"(a[mt][0]), "r"(a[mt][1]), "r"(a[mt][2]), "r"(a[mt][3]),
                          "r"(b[nt][0]), "r"(b[nt][1]));
        }

        // generate next A tile (FMA/ALU pipes, overlaps tensor work); visible after next sync
        if (kt + 1 < KITERS) compute_A(kt + 1, (kt + 1) & 1);
    }

    // epilogue
    #pragma unroll
    for (int mt = 0; mt < 4; mt++){
        int mrow0 = m0 + wm*64 + mt*16 + (lane >> 2);
        #pragma unroll
        for (int nt = 0; nt < 4; nt++){
            int n = wn*32 + nt*8 + (lane & 3)*2;
            #pragma unroll
            for (int half = 0; half < 2; half++){
                int m = mrow0 + half*8;
                if (m < M){
                    size_t p = (size_t)m*DD + n;
                    float v0 = acc[mt][nt][half*2 + 0];
                    float v1 = acc[mt][nt][half*2 + 1];
                    if (mode == 0){
                        C[p]   = v0;
                        C[p+1] = v1;
                    } else {
                        hout[p]   = hin[p]   + EPS_F*(C[p]   + v0);
                        hout[p+1] = hin[p+1] + EPS_F*(C[p+1] + v1);
                    }
                }
            }
        }
    }
}

// ---------------- launch ----------------
extern "C" void kernel_launch(void* const* d_in, const int* in_sizes, int n_in,
                              void* d_out, int out_size)
{
    const float* x   = (const float*)d_in[0];
    const void*  ei  = d_in[1];
    const float* bwl = (const float*)d_in[2];
    const float* swl = (const float*)d_in[3];
    const float* bwc = (const float*)d_in[4];
    const float* swc = (const float*)d_in[5];
    float* out = (float*)d_out;

    int E = in_sizes[1] / 2;

    cudaFuncSetAttribute(gemm_kernel, cudaFuncAttributeMaxDynamicSharedMemorySize, GSMEM_TOTAL);

    void *p_Wl, *p_Wc, *p_out, *p_agg, *p_h1;
    cudaGetSymbolAddress(&p_Wl,  g_Wl);
    cudaGetSymbolAddress(&p_Wc,  g_Wc);
    cudaGetSymbolAddress(&p_out, g_out);
    cudaGetSymbolAddress(&p_agg, g_agg);
    cudaGetSymbolAddress(&p_h1,  g_h1);

    const int MB = (NN + BM - 1) / BM;   // 391 GEMM blocks

    // NOTE: ncu captures launch index 3 -> put the first GEMM there for profiling.
    zero_kernel<<<(NN + 255)/256, 256>>>();                                   // 0
    detect_kernel<<<8, 256>>>((const int*)ei);                                // 1
    pack_kernel<<<(DD*KTOT + 255)/256, 256>>>(bwl, swl, bwc, swc);            // 2
    gemm_kernel<<<MB, 256, GSMEM_TOTAL>>>(x, (const __nv_bfloat16*)p_Wl,      // 3 (profiled)
                                          (float*)p_out, nullptr, nullptr, NN, 0);

    // ---- graph preprocessing ----
    deg_kernel<<<(E + 255)/256, 256>>>(ei, E);
    partial_kernel<<<NBLK, SCAN_B>>>();
    scanpart_kernel<<<1, SCAN_B>>>();
    rowptr_kernel<<<NBLK, SCAN_B>>>();
    fill_kernel<<<(E + 255)/256, 256>>>(ei, E);

    // ---- Euler step 1 (branch 2 + fused update): h1 = x + eps*(out + KAN_c(agg(x))) ----
    agg_kernel<<<(NN + 7)/8, 256>>>(x);
    gemm_kernel<<<MB, 256, GSMEM_TOTAL>>>((const float*)p_agg, (const __nv_bfloat16*)p_Wc,
                                          (float*)p_out, x, (float*)p_h1, NN, 1);

    // ---- Euler step 2: out = h1 + eps*(KAN_l(h1) + KAN_c(agg(h1))) ----
    gemm_kernel<<<MB, 256, GSMEM_TOTAL>>>((const float*)p_h1, (const __nv_bfloat16*)p_Wl,
                                          (float*)p_out, nullptr, nullptr, NN, 0);
    agg_kernel<<<(NN + 7)/8, 256>>>((const float*)p_h1);
    gemm_kernel<<<MB, 256, GSMEM_TOTAL>>>((const float*)p_agg, (const __nv_bfloat16*)p_Wc,
                                          (float*)p_out, (const float*)p_h1, out, NN, 1);
}